// round 1
// baseline (speedup 1.0000x reference)
#include <cuda_runtime.h>
#include <math.h>

// Problem constants (fixed shapes from reference setup_inputs)
#define BCLS   64      // total_classes
#define NVIEW  128
#define DIM    128
#define NROWS  (BCLS * NVIEW)   // 8192

#define TILE    64     // rows per block / cols per tile
#define NBLKS   (NROWS / TILE)  // 128
#define NTILES  (NROWS / TILE)  // 128

// Scratch: normalized features, transposed [k][row] for coalesced tile loads
__device__ float g_featT[DIM * NROWS];     // 4 MB
__device__ float g_partial[NBLKS];

// ---------------------------------------------------------------------------
// Kernel 1: normalize rows of x [8192,128] and store transposed [128,8192]
// 256 blocks x 256 threads, 32 rows per block, smem transpose (pad to 129
// floats/row -> conflict-free on both phases).
// ---------------------------------------------------------------------------
__global__ __launch_bounds__(256) void norm_transpose_kernel(const float* __restrict__ x) {
    __shared__ float tile[32][129];
    __shared__ float inv[32];
    const int t = threadIdx.x;
    const int row0 = blockIdx.x * 32;

    // coalesced load: 32 rows x 128 cols
    #pragma unroll
    for (int i = 0; i < 16; i++) {
        int idx = i * 256 + t;
        int r = idx >> 7;        // 0..31
        int k = idx & 127;       // 0..127
        tile[r][k] = x[(row0 + r) * DIM + k];
    }
    __syncthreads();

    if (t < 32) {
        float ss = 0.0f;
        #pragma unroll 8
        for (int k = 0; k < DIM; k++) { float v = tile[t][k]; ss += v * v; }
        inv[t] = 1.0f / fmaxf(sqrtf(ss), 1e-12f);
    }
    __syncthreads();

    // coalesced transposed store: consecutive t -> consecutive r for fixed k
    #pragma unroll
    for (int i = 0; i < 16; i++) {
        int idx = i * 256 + t;
        int r = idx & 31;        // 0..31
        int k = idx >> 5;        // 0..127
        g_featT[k * NROWS + row0 + r] = tile[r][k] * inv[r];
    }
}

// ---------------------------------------------------------------------------
// Kernel 2: fused sim + exp + masked row sums.
// Grid: 128 blocks (64 rows each). Block: 256 threads = 16x16, 4x4 microtile.
// smem: As[128][64] (block's rows, loaded once) + Bs[128][64] per col tile.
// Row max is analytically 1.0 (normalized features): logits = sim - 1.
// Col class for tile-local col c is y[c] (64-aligned tiles): mask is a
// per-thread int compare.
// ---------------------------------------------------------------------------
__global__ __launch_bounds__(256) void fused_sim_loss_kernel(const int* __restrict__ y) {
    extern __shared__ float smem[];
    float* As = smem;                 // DIM*TILE = 8192 floats
    float* Bs = smem + DIM * TILE;    // 8192 floats

    __shared__ int   ys[BCLS];
    __shared__ float losses[TILE];

    const int t  = threadIdx.x;
    const int tx = t & 15;            // col group 0..15
    const int ty = t >> 4;            // row group 0..15
    const int row0 = blockIdx.x * TILE;

    // Load A tile (rows of this block), transposed layout As[k][r]
    #pragma unroll
    for (int i = 0; i < 8; i++) {
        int idx = i * 256 + t;
        int k  = idx >> 4;
        int r4 = (idx & 15) * 4;
        *(float4*)&As[k * TILE + r4] =
            *(const float4*)&g_featT[k * NROWS + row0 + r4];
    }
    if (t < BCLS) ys[t] = y[t];
    __syncthreads();

    // classes for this thread's 4 rows / 4 cols (cols identical every tile)
    int rl[4], cl[4];
    #pragma unroll
    for (int ii = 0; ii < 4; ii++) {
        rl[ii] = ys[(row0 + ty * 4 + ii) >> 7];
        cl[ii] = ys[tx * 4 + ii];
    }

    float s_all[4] = {0.f, 0.f, 0.f, 0.f};
    float s_pos[4] = {0.f, 0.f, 0.f, 0.f};

    for (int tile_i = 0; tile_i < NTILES; tile_i++) {
        const int col0 = tile_i * TILE;
        __syncthreads();   // protect Bs from previous iteration's readers
        #pragma unroll
        for (int i = 0; i < 8; i++) {
            int idx = i * 256 + t;
            int k  = idx >> 4;
            int c4 = (idx & 15) * 4;
            *(float4*)&Bs[k * TILE + c4] =
                *(const float4*)&g_featT[k * NROWS + col0 + c4];
        }
        __syncthreads();

        float acc[4][4];
        #pragma unroll
        for (int ii = 0; ii < 4; ii++)
            #pragma unroll
            for (int jj = 0; jj < 4; jj++) acc[ii][jj] = 0.0f;

        #pragma unroll 8
        for (int k = 0; k < DIM; k++) {
            float4 a = *(float4*)&As[k * TILE + ty * 4];
            float4 b = *(float4*)&Bs[k * TILE + tx * 4];
            acc[0][0] += a.x * b.x; acc[0][1] += a.x * b.y;
            acc[0][2] += a.x * b.z; acc[0][3] += a.x * b.w;
            acc[1][0] += a.y * b.x; acc[1][1] += a.y * b.y;
            acc[1][2] += a.y * b.z; acc[1][3] += a.y * b.w;
            acc[2][0] += a.z * b.x; acc[2][1] += a.z * b.y;
            acc[2][2] += a.z * b.z; acc[2][3] += a.z * b.w;
            acc[3][0] += a.w * b.x; acc[3][1] += a.w * b.y;
            acc[3][2] += a.w * b.z; acc[3][3] += a.w * b.w;
        }

        // epilogue: exp(sim - 1), masked accumulation
        #pragma unroll
        for (int ii = 0; ii < 4; ii++) {
            #pragma unroll
            for (int jj = 0; jj < 4; jj++) {
                float e = __expf(acc[ii][jj] - 1.0f);
                s_all[ii] += e;
                if (rl[ii] == cl[jj]) s_pos[ii] += e;
            }
        }
    }

    // Deterministic block reduction: redA/redP[tx][row] in reused smem
    __syncthreads();
    float* redA = smem;               // 16*64
    float* redP = smem + 16 * TILE;   // 16*64
    #pragma unroll
    for (int ii = 0; ii < 4; ii++) {
        redA[tx * TILE + ty * 4 + ii] = s_all[ii];
        redP[tx * TILE + ty * 4 + ii] = s_pos[ii];
    }
    __syncthreads();
    if (t < TILE) {
        float a = 0.f, p = 0.f;
        #pragma unroll
        for (int j = 0; j < 16; j++) {
            a += redA[j * TILE + t];
            p += redP[j * TILE + t];
        }
        // loss = -log( pos / (all + eps) + eps )
        losses[t] = -logf(p / (a + 1e-8f) + 1e-8f);
    }
    __syncthreads();
    if (t == 0) {
        float s = 0.f;
        #pragma unroll 8
        for (int i = 0; i < TILE; i++) s += losses[i];
        g_partial[blockIdx.x] = s;
    }
}

// ---------------------------------------------------------------------------
// Kernel 3: deterministic final reduction in double, write mean.
// ---------------------------------------------------------------------------
__global__ void finalize_kernel(float* __restrict__ out) {
    double s = 0.0;
    for (int i = 0; i < NBLKS; i++) s += (double)g_partial[i];
    out[0] = (float)(s / (double)NROWS);
}

extern "C" void kernel_launch(void* const* d_in, const int* in_sizes, int n_in,
                              void* d_out, int out_size) {
    const float* x = (const float*)d_in[0];   // [64,128,128] f32
    const int*   y = (const int*)d_in[1];     // [64] i32
    float* out = (float*)d_out;

    static int smem_set = 0;
    const int dyn_smem = 2 * DIM * TILE * (int)sizeof(float);  // 64 KB
    if (!smem_set) {
        cudaFuncSetAttribute(fused_sim_loss_kernel,
                             cudaFuncAttributeMaxDynamicSharedMemorySize, dyn_smem);
        smem_set = 1;
    }

    norm_transpose_kernel<<<NROWS / 32, 256>>>(x);
    fused_sim_loss_kernel<<<NBLKS, 256, dyn_smem>>>(y);
    finalize_kernel<<<1, 1>>>(out);
}

// round 4
// speedup vs baseline: 8.2566x; 8.2566x over previous
#include <cuda_runtime.h>
#include <cuda_bf16.h>
#include <stdint.h>
#include <math.h>

typedef unsigned int u32;

// Fixed problem shape
#define NROWS 8192
#define DIM   128
#define BCLS  64
#define RBLK  128          // rows per block (== n_view -> one class per block)
#define CTILE 128          // cols per tile
#define NCHALF 2
#define CHALF (NROWS/NCHALF)           // 4096
#define NTILES (CHALF/CTILE)           // 32

__device__ __align__(16) __nv_bfloat16 g_featb[NROWS * DIM];   // normalized, bf16
__device__ float g_all[NCHALF][NROWS];
__device__ float g_pos[NCHALF][NROWS];

// ---------------------------------------------------------------------------
// PTX helpers
// ---------------------------------------------------------------------------
__device__ __forceinline__ void cp16(u32 dst, const void* src) {
    asm volatile("cp.async.cg.shared.global [%0], [%1], 16;\n" :: "r"(dst), "l"(src));
}
__device__ __forceinline__ void cp_commit() {
    asm volatile("cp.async.commit_group;\n" ::: "memory");
}
template <int N>
__device__ __forceinline__ void cp_wait() {
    asm volatile("cp.async.wait_group %0;\n" :: "n"(N) : "memory");
}

__device__ __forceinline__ void ldsm4(u32& q0, u32& q1, u32& q2, u32& q3, u32 addr) {
    asm volatile("ldmatrix.sync.aligned.m8n8.x4.shared.b16 {%0,%1,%2,%3}, [%4];"
                 : "=r"(q0), "=r"(q1), "=r"(q2), "=r"(q3) : "r"(addr));
}

__device__ __forceinline__ void mma16816(float* dacc, u32 qa0, u32 qa1,
                                         u32 qa2, u32 qa3, u32 qb0, u32 qb1) {
    asm volatile("mma.sync.aligned.m16n8k16.row.col.f32.bf16.bf16.f32 "
                 "{%0,%1,%2,%3}, {%4,%5,%6,%7}, {%8,%9}, {%0,%1,%2,%3};"
                 : "+f"(dacc[0]), "+f"(dacc[1]), "+f"(dacc[2]), "+f"(dacc[3])
                 : "r"(qa0), "r"(qa1), "r"(qa2), "r"(qa3), "r"(qb0), "r"(qb1));
}

// ---------------------------------------------------------------------------
// Kernel 1: L2-normalize rows (fp32 math), emit bf16 [8192][128]
// One warp per row.
// ---------------------------------------------------------------------------
__global__ __launch_bounds__(256) void normalize_kernel(const float* __restrict__ x) {
    int gw   = (blockIdx.x * 256 + threadIdx.x) >> 5;   // global warp = row
    int lane = threadIdx.x & 31;
    float4 v = ((const float4*)(x + (size_t)gw * DIM))[lane];
    float ss = v.x * v.x + v.y * v.y + v.z * v.z + v.w * v.w;
    #pragma unroll
    for (int o = 16; o; o >>= 1) ss += __shfl_xor_sync(0xffffffffu, ss, o);
    float inv = 1.0f / fmaxf(sqrtf(ss), 1e-12f);
    __nv_bfloat162 p0 = __floats2bfloat162_rn(v.x * inv, v.y * inv);
    __nv_bfloat162 p1 = __floats2bfloat162_rn(v.z * inv, v.w * inv);
    __nv_bfloat162* dst = (__nv_bfloat162*)(g_featb + (size_t)gw * DIM);
    dst[lane * 2 + 0] = p0;
    dst[lane * 2 + 1] = p1;
}

// ---------------------------------------------------------------------------
// Tile loader: 128 rows x 128 bf16 (256B/row) -> smem with XOR-16B-chunk
// swizzle: chunk c of row r stored at r*256 + ((c ^ (r&7)) << 4).
// ---------------------------------------------------------------------------
__device__ __forceinline__ void load_tile(u32 sbase,
                                          const __nv_bfloat16* gbase, int tid) {
    #pragma unroll
    for (int i = 0; i < 8; i++) {
        int id = i * 256 + tid;
        int r  = id >> 4;
        int c  = id & 15;
        u32 dst = sbase + r * 256 + ((c ^ (r & 7)) << 4);
        const char* src = (const char*)gbase + r * 256 + c * 16;
        cp16(dst, src);
    }
}

// ---------------------------------------------------------------------------
// Kernel 2: fused bf16 MMA sim + exp + masked row sums.
// Grid (2, 64): y = row block (128 rows, single class), x = column half.
// Block 256 threads = 8 warps, warp w owns rows w*16..w*16+15, all 128 cols
// of each tile. Double-buffered cp.async B tiles.
// ---------------------------------------------------------------------------
__global__ __launch_bounds__(256) void fused_kernel(const int* __restrict__ y) {
    extern __shared__ __align__(1024) char smem[];
    u32 sA  = (u32)__cvta_generic_to_shared(smem);
    u32 sB0 = sA + 32768;
    u32 sB1 = sA + 65536;
    __shared__ int ys[BCLS];

    const int tid  = threadIdx.x;
    const int lane = tid & 31;
    const int w    = tid >> 5;
    const int rowblk = blockIdx.y;
    const int chalf  = blockIdx.x;
    const int myclass = __ldg(y + rowblk);   // all 128 rows of block share class

    if (tid < BCLS) ys[tid] = y[tid];

    // prologue: A tile + first B tile (one cp.async group)
    load_tile(sA,  g_featb + (size_t)rowblk * RBLK * DIM, tid);
    load_tile(sB0, g_featb + (size_t)(chalf * CHALF) * DIM, tid);
    cp_commit();
    __syncthreads();   // ys visible

    // Column-class masks: global col = chalf*4096 + t*128 + j; col%64 = j%64,
    // identical for every tile. Thread's cols per n-tile nt: nt*8 + 2*(lane&3) {+1}.
    unsigned m0bits = 0, m1bits = 0;
    #pragma unroll
    for (int nt = 0; nt < 16; nt++) {
        int j0 = nt * 8 + 2 * (lane & 3);
        if (ys[j0 & 63]       == myclass) m0bits |= 1u << nt;
        if (ys[(j0 + 1) & 63] == myclass) m1bits |= 1u << nt;
    }

    // ldmatrix address precompute: addr = Q + ((s<<5) ^ kE)
    const int lr = (lane & 7) | (((lane >> 3) & 1) << 3);  // row within 16
    const int hi = lane >> 4;                               // k-chunk select
    const u32 kE = (u32)((lr & 6) << 4);
    const u32 ob = (u32)((hi ^ (lr & 1)) << 4);
    const u32 QA  = sA  + (u32)(w * 16 + lr) * 256 + ob;
    const u32 QB0 = sB0 + (u32)lr * 256 + ob;
    const u32 QB1 = sB1 + (u32)lr * 256 + ob;

    float sAll0 = 0.f, sAll1 = 0.f, sPos0 = 0.f, sPos1 = 0.f;

    for (int t = 0; t < NTILES; t++) {
        // prefetch next B tile into the other buffer
        if (t + 1 < NTILES) {
            u32 sBnext = (t & 1) ? sB0 : sB1;
            load_tile(sBnext,
                      g_featb + (size_t)(chalf * CHALF + (t + 1) * CTILE) * DIM, tid);
            cp_commit();
            cp_wait<1>();   // current tile's group done, next in flight
        } else {
            cp_wait<0>();
        }
        __syncthreads();

        float acc[16][4];
        #pragma unroll
        for (int i = 0; i < 16; i++) {
            #pragma unroll
            for (int j = 0; j < 4; j++) acc[i][j] = 0.f;
        }

        const u32 QB = (t & 1) ? QB1 : QB0;

        #pragma unroll
        for (int s = 0; s < 8; s++) {
            const u32 off = ((u32)(s << 5)) ^ kE;
            u32 qa0, qa1, qa2, qa3;
            ldsm4(qa0, qa1, qa2, qa3, QA + off);
            #pragma unroll
            for (int p = 0; p < 8; p++) {
                u32 qn0, qn1, qn2, qn3;
                ldsm4(qn0, qn1, qn2, qn3, QB + (u32)(p * 4096) + off);
                mma16816(acc[2 * p],     qa0, qa1, qa2, qa3, qn0, qn2);
                mma16816(acc[2 * p + 1], qa0, qa1, qa2, qa3, qn1, qn3);
            }
        }

        // epilogue: exp(sim - 1), masked accumulation (row max == 1 analytically;
        // the pos/(all+eps) ratio is shift-invariant regardless)
        #pragma unroll
        for (int nt = 0; nt < 16; nt++) {
            float e0 = __expf(acc[nt][0] - 1.0f);
            float e1 = __expf(acc[nt][1] - 1.0f);
            float e2 = __expf(acc[nt][2] - 1.0f);
            float e3 = __expf(acc[nt][3] - 1.0f);
            sAll0 += e0 + e1;
            sAll1 += e2 + e3;
            if ((m0bits >> nt) & 1) { sPos0 += e0; sPos1 += e2; }
            if ((m1bits >> nt) & 1) { sPos0 += e1; sPos1 += e3; }
        }
        __syncthreads();   // done reading current B buffer
    }

    // reduce across the 4 lanes of each row-quad (deterministic)
    #pragma unroll
    for (int o = 1; o <= 2; o <<= 1) {
        sAll0 += __shfl_xor_sync(0xffffffffu, sAll0, o);
        sAll1 += __shfl_xor_sync(0xffffffffu, sAll1, o);
        sPos0 += __shfl_xor_sync(0xffffffffu, sPos0, o);
        sPos1 += __shfl_xor_sync(0xffffffffu, sPos1, o);
    }
    if ((lane & 3) == 0) {
        int g  = lane >> 2;
        int r0 = rowblk * RBLK + w * 16 + g;
        g_all[chalf][r0]     = sAll0;
        g_pos[chalf][r0]     = sPos0;
        g_all[chalf][r0 + 8] = sAll1;
        g_pos[chalf][r0 + 8] = sPos1;
    }
}

// ---------------------------------------------------------------------------
// Kernel 3: per-row loss, deterministic tree reduce, mean.
// ---------------------------------------------------------------------------
__global__ __launch_bounds__(1024) void finalize_kernel(float* __restrict__ out) {
    __shared__ float red[1024];
    int t = threadIdx.x;
    float s = 0.f;
    #pragma unroll
    for (int i = 0; i < 8; i++) {
        int r = t * 8 + i;
        float all = g_all[0][r] + g_all[1][r];
        float pos = g_pos[0][r] + g_pos[1][r];
        s += -logf(pos / (all + 1e-8f) + 1e-8f);
    }
    red[t] = s;
    __syncthreads();
    #pragma unroll
    for (int o = 512; o; o >>= 1) {
        if (t < o) red[t] += red[t + o];
        __syncthreads();
    }
    if (t == 0) out[0] = red[0] / (float)NROWS;
}

extern "C" void kernel_launch(void* const* d_in, const int* in_sizes, int n_in,
                              void* d_out, int out_size) {
    const float* x = (const float*)d_in[0];   // [64,128,128] f32
    const int*   y = (const int*)d_in[1];     // [64] i32
    float* out = (float*)d_out;

    static int attr_set = 0;
    const int dyn_smem = 96 * 1024;
    if (!attr_set) {
        cudaFuncSetAttribute(fused_kernel,
                             cudaFuncAttributeMaxDynamicSharedMemorySize, dyn_smem);
        attr_set = 1;
    }

    normalize_kernel<<<NROWS / 8, 256>>>(x);
    fused_kernel<<<dim3(NCHALF, NROWS / RBLK), 256, dyn_smem>>>(y);
    finalize_kernel<<<1, 1024>>>(out);
}